// round 6
// baseline (speedup 1.0000x reference)
#include <cuda_runtime.h>
#include <cuda_bf16.h>

// Problem constants
#define SEQn 256
#define Bn   64
#define Hn   512
#define Ln   4

#define NJ    16      // output columns per block
#define NBC   32      // blocks per (t,l) pair (NBC*NJ == Hn)
#define NTHR  512     // 16 warps -> 4 warps per SMSP
#define KC    128     // K-chunk staged in shared

#define WPAD  516     // padded W row stride (floats): %32==4, %4==0 -> CF LDS.128
#define APAD  132     // padded A row stride (floats): %32==4, %4==0 -> CF LDS.128

// Dynamic smem: W tiles [2][NJ][WPAD] + double-buffered A chunk [2][Bn][APAD]
#define SW_FLOATS  (2 * NJ * WPAD)
#define SA_FLOATS  (Bn * APAD)
#define SMEM_FLOATS (SW_FLOATS + 2 * SA_FLOATS)
#define SMEM_BYTES  (SMEM_FLOATS * 4)

// Packed dual-fp32 FMA (sm_100+): d = a * w + d, elementwise on {lo,hi}
#define FMA2(d, a, w) \
    asm("fma.rn.f32x2 %0, %1, %2, %3;" : "=l"(d) : "l"(a), "l"(w), "l"(d))

// h(-1) = 0. Never written; device globals are zero-initialized.
__device__ float g_zero[Bn * Hn];

__device__ __forceinline__ float hsum2(unsigned long long v) {
    float lo = __uint_as_float((unsigned int)(v & 0xffffffffull));
    float hi = __uint_as_float((unsigned int)(v >> 32));
    return lo + hi;
}

// One launch per wavefront phase p = t + layer. All (t,layer) pairs on the
// antidiagonal are independent; dependencies live in phase p-1 and are
// enforced by launch ordering. No inter-block synchronization anywhere.
__global__ __launch_bounds__(NTHR, 1)
void rnn_phase_kernel(const float* __restrict__ x,
                      const float* __restrict__ w_ih,
                      const float* __restrict__ b_ih,
                      const float* __restrict__ w_hh,
                      const float* __restrict__ b_hh,
                      float* __restrict__ out,
                      int p, int lmin)
{
    const int layer = lmin + (blockIdx.x >> 5);
    const int t     = p - layer;
    const int cb    = blockIdx.x & (NBC - 1);
    const int j0    = cb * NJ;
    const int tid   = threadIdx.x;

    // Lane tiling: lane = (bl<<2)|jl. Warp: wid = (wj<<2)|wb.
    const int lane = tid & 31;
    const int wid  = tid >> 5;
    const int jl   = lane & 3;           // 4 j-lanes (share A row -> A broadcast x4)
    const int bl   = lane >> 2;          // 8 b-lanes (share W row -> W broadcast x8)
    const int wb   = wid & 3;            // 4 b-tiles of 16
    const int wj   = wid >> 2;           // 4 j-tiles of 4

    const int B0 = wb * 16 + bl;         // thread's two batch rows
    const int B1 = B0 + 8;
    const int J  = wj * 4 + jl;          // thread's single local col (within NJ)

    extern __shared__ float smem_dyn[];
    float* sW = smem_dyn;                          // [2][NJ][WPAD]: ih then hh
    float* sA0 = smem_dyn + SW_FLOATS;             // A buffer 0
    float* sA1 = smem_dyn + SW_FLOATS + SA_FLOATS; // A buffer 1

    float* outputs = out;                     // [SEQ][B][H]
    float* states  = out + SEQn * Bn * Hn;    // [SEQ][L][B][H]

    const float* inpA = (layer == 0)
        ? (x + (size_t)t * Bn * Hn)
        : (states + (size_t)(t * Ln + (layer - 1)) * Bn * Hn);
    const float* hA = (t == 0)
        ? g_zero
        : (states + (size_t)((t - 1) * Ln + layer) * Bn * Hn);

    // ---- Prologue ----
    // Weights: 2 matrices * NJ rows * 128 float4 = 4096 float4; 8 per thread.
    // LDGs batched (MLP=8, L2-resident) then STS into padded tiles.
    {
        float4 wtmp[8];
        #pragma unroll
        for (int u = 0; u < 8; ++u) {
            int i  = u * NTHR + tid;
            int m  = i >> 11;                 // 0: ih, 1: hh
            int r  = i & 2047;
            int jj = r >> 7;                  // row within tile
            int q  = r & 127;                 // float4 index within row
            const float* src = (m ? w_hh : w_ih);
            wtmp[u] = ((const float4*)src)[(size_t)(layer * Hn + j0 + jj) * (Hn / 4) + q];
        }
        #pragma unroll
        for (int u = 0; u < 8; ++u) {
            int i  = u * NTHR + tid;
            int m  = i >> 11;
            int r  = i & 2047;
            int jj = r >> 7;
            int q  = r & 127;
            *(float4*)(sW + m * NJ * WPAD + jj * WPAD + q * 4) = wtmp[u];
        }
    }

    // Chunk-0 activation prefetch: 2048 float4 per chunk; 4 per thread.
    // row = f4>>5 (32 float4 per 128-float row), col4 = f4&31.
    float4 pf[4];
    #pragma unroll
    for (int u = 0; u < 4; ++u) {
        int f4 = u * NTHR + tid;
        pf[u] = ((const float4*)inpA)[(f4 >> 5) * (Hn / 4) + (f4 & 31)];
    }
    #pragma unroll
    for (int u = 0; u < 4; ++u) {
        int f4 = u * NTHR + tid;
        *(float4*)(sA0 + (f4 >> 5) * APAD + (f4 & 31) * 4) = pf[u];   // CF STS.128
    }

    // 4 accumulator chains: {out0,out1} x {even-k-pair, odd-k-pair}
    unsigned long long acc0a, acc0b, acc1a, acc1b;
    {
        int jb = layer * Hn + j0 + J;
        float f = b_ih[jb] + b_hh[jb];
        acc0a = (unsigned long long)__float_as_uint(f);   // {bias, 0}
        acc1a = acc0a;
        acc0b = 0ull;
        acc1b = 0ull;
    }
    __syncthreads();

    // 8 K-chunks: 0..3 over inp (Wih), 4..7 over h (Whh). Double-buffered:
    // one barrier per chunk; STS of chunk cc+1 overlaps compute of chunk cc.
    for (int cc = 0; cc < 8; ++cc) {
        float* bufC = (cc & 1) ? sA1 : sA0;
        float* bufN = (cc & 1) ? sA0 : sA1;

        if (cc < 7) {          // issue next-chunk LDGs before compute (hidden)
            const float* Asrc = ((cc + 1) < 4) ? inpA : hA;
            int koff4 = ((cc + 1) & 3) * (KC / 4);
            #pragma unroll
            for (int u = 0; u < 4; ++u) {
                int f4 = u * NTHR + tid;
                pf[u] = ((const float4*)Asrc)[(f4 >> 5) * (Hn / 4) + koff4 + (f4 & 31)];
            }
        }

        const float* aR0 = bufC + B0 * APAD;
        const float* aR1 = bufC + B1 * APAD;
        const float* wR  = sW + (cc >> 2) * (NJ * WPAD) + J * WPAD + (cc & 3) * KC;

        #pragma unroll 8
        for (int kk = 0; kk < KC; kk += 4) {
            // Each ulonglong2 = two packed f32x2 covering 4 consecutive k.
            ulonglong2 A0 = *(const ulonglong2*)(aR0 + kk);  // 8 addrs x4 bcast, CF
            ulonglong2 A1 = *(const ulonglong2*)(aR1 + kk);
            ulonglong2 W  = *(const ulonglong2*)(wR  + kk);  // 4 addrs x8 bcast, CF
            FMA2(acc0a, A0.x, W.x);
            FMA2(acc0b, A0.y, W.y);
            FMA2(acc1a, A1.x, W.x);
            FMA2(acc1b, A1.y, W.y);
        }

        if (cc < 7) {          // stage next chunk into the other buffer
            #pragma unroll
            for (int u = 0; u < 4; ++u) {
                int f4 = u * NTHR + tid;
                *(float4*)(bufN + (f4 >> 5) * APAD + (f4 & 31) * 4) = pf[u];
            }
        }
        __syncthreads();
    }

    // Horizontal reduce + activation + writeback (2 outputs/thread)
    float r0 = tanhf(hsum2(acc0a) + hsum2(acc0b));
    float r1 = tanhf(hsum2(acc1a) + hsum2(acc1b));
    {
        size_t s0 = ((size_t)(t * Ln + layer) * Bn + B0) * Hn + j0 + J;
        size_t s1 = ((size_t)(t * Ln + layer) * Bn + B1) * Hn + j0 + J;
        states[s0] = r0;
        states[s1] = r1;
        if (layer == Ln - 1) {
            outputs[((size_t)t * Bn + B0) * Hn + j0 + J] = r0;
            outputs[((size_t)t * Bn + B1) * Hn + j0 + J] = r1;
        }
    }
}

extern "C" void kernel_launch(void* const* d_in, const int* in_sizes, int n_in,
                              void* d_out, int out_size) {
    const float* x    = (const float*)d_in[0];   // [SEQ,B,H]
    const float* w_ih = (const float*)d_in[1];   // [L,H,H]
    const float* b_ih = (const float*)d_in[2];   // [L,H]
    const float* w_hh = (const float*)d_in[3];   // [L,H,H]
    const float* b_hh = (const float*)d_in[4];   // [L,H]
    float* out = (float*)d_out;                  // [SEQ,B,H] outputs ++ [SEQ*L,B,H] states

    cudaFuncSetAttribute(rnn_phase_kernel,
                         cudaFuncAttributeMaxDynamicSharedMemorySize, SMEM_BYTES);

    // Wavefront over launches: phase p = t + layer, p = 0 .. SEQ+L-2.
    // All pairs on an antidiagonal are independent; cross-phase dependencies
    // are enforced by stream/launch order (graph-capture safe, no atomics).
    for (int p = 0; p < SEQn + Ln - 1; ++p) {
        int lmin = (p - (SEQn - 1) > 0) ? (p - (SEQn - 1)) : 0;
        int lmax = (p < Ln - 1) ? p : (Ln - 1);
        int nl   = lmax - lmin + 1;
        rnn_phase_kernel<<<NBC * nl, NTHR, SMEM_BYTES>>>(
            x, w_ih, b_ih, w_hh, b_hh, out, p, lmin);
    }
}

// round 9
// speedup vs baseline: 1.2613x; 1.2613x over previous
#include <cuda_runtime.h>
#include <cuda_bf16.h>

// Problem constants
#define SEQn 256
#define Bn   64
#define Hn   512
#define Ln   4

#define NJ    16      // output columns per block
#define NBC   32      // blocks per layer (NBC*NJ == Hn)
#define NTHR  256     // 8 warps, 2 per SMSP
#define KC    128     // K-chunk staged in shared

#define WPAD  516     // padded W row stride (floats): %32==4, %4==0 -> CF LDS.128
#define APAD  132     // padded A row stride (floats): %32==4, %4==0 -> CF LDS.128

// Dynamic smem: W tiles [2][NJ][WPAD] + double-buffered A chunk [2][Bn][APAD]
#define SW_FLOATS   (2 * NJ * WPAD)
#define SA_FLOATS   (Bn * APAD)
#define SMEM_FLOATS (SW_FLOATS + 2 * SA_FLOATS)
#define SMEM_BYTES  (SMEM_FLOATS * 4)

// Packed dual-fp32 FMA (sm_100+): d = a * w + d, elementwise on {lo,hi}
#define FMA2(d, a, w) \
    asm("fma.rn.f32x2 %0, %1, %2, %3;" : "=l"(d) : "l"(a), "l"(w), "l"(d))

// .cg (L2-only) accessors for the cross-SM-shared activation buffer.
// L1 is NOT coherent across SMs and persists for the whole persistent kernel
// (no per-launch flush), so any L1 hit on another block's write is stale.
// These lines have zero L1 reuse anyway (streamed once), so .cg is free.
__device__ __forceinline__ float4 ld_cg_f4(const float* p) {
    float4 v;
    asm volatile("ld.global.cg.v4.f32 {%0,%1,%2,%3}, [%4];"
                 : "=f"(v.x), "=f"(v.y), "=f"(v.z), "=f"(v.w)
                 : "l"(p));
    return v;
}
__device__ __forceinline__ void st_cg_f32(float* p, float v) {
    asm volatile("st.global.cg.f32 [%0], %1;" :: "l"(p), "f"(v) : "memory");
}

// Persistent device state: per-(layer,t) completion counters, zeroed by a
// prologue kernel on every launch (graph-replay safe). Only 4 KB static.
__device__ int g_cnt[Ln * SEQn];

__global__ void zero_cnt_kernel() {
    g_cnt[threadIdx.x] = 0;   // launched with exactly Ln*SEQn = 1024 threads
}

__device__ __forceinline__ float hsum2(unsigned long long v) {
    float lo = __uint_as_float((unsigned int)(v & 0xffffffffull));
    float hi = __uint_as_float((unsigned int)(v >> 32));
    return lo + hi;
}

__global__ __launch_bounds__(NTHR, 1)
void rnn_kernel(const float* __restrict__ x,
                const float* __restrict__ w_ih,
                const float* __restrict__ b_ih,
                const float* __restrict__ w_hh,
                const float* __restrict__ b_hh,
                float* __restrict__ out)
{
    const int layer = blockIdx.x >> 5;   // /NBC
    const int cb    = blockIdx.x & (NBC - 1);
    const int j0    = cb * NJ;
    const int tid   = threadIdx.x;

    // Lane tiling (round-5 core): lane = (bl<<2)|jl ; warp = (wj<<2)|wb
    const int lane = tid & 31;
    const int wid  = tid >> 5;
    const int jl   = lane & 3;           // 4 j-lanes
    const int bl   = lane >> 2;          // 8 b-lanes
    const int wb   = wid & 3;            // 4 b-tiles of 16
    const int wj   = wid >> 2;           // 2 j-tiles of 8

    const int B0 = wb * 16 + bl;         // thread's two batch rows
    const int B1 = B0 + 8;
    const int J0 = wj * 8 + jl;          // thread's two local cols (within NJ)
    const int J1 = J0 + 4;

    extern __shared__ float smem_dyn[];
    float* sW  = smem_dyn;                          // [2][NJ][WPAD]: ih then hh
    float* sA0 = smem_dyn + SW_FLOATS;              // A buffer 0
    float* sA1 = smem_dyn + SW_FLOATS + SA_FLOATS;  // A buffer 1

    float* outputs = out;                     // [SEQ][B][H]
    float* states  = out + SEQn * Bn * Hn;    // [SEQ][L][B][H]

    // ---- One-time: weights into padded shared tiles (reused for all 256 t) ----
    {
        float4 wtmp[16];   // 2 matrices * NJ rows * 128 float4 = 4096; 16/thread
        #pragma unroll
        for (int u = 0; u < 16; ++u) {
            int i  = u * NTHR + tid;
            int m  = i >> 11;                 // 0: ih, 1: hh
            int r  = i & 2047;
            int jj = r >> 7;                  // row within tile
            int q  = r & 127;                 // float4 index within row
            const float* src = (m ? w_hh : w_ih);
            wtmp[u] = ((const float4*)src)[(size_t)(layer * Hn + j0 + jj) * (Hn / 4) + q];
        }
        #pragma unroll
        for (int u = 0; u < 16; ++u) {
            int i  = u * NTHR + tid;
            int m  = i >> 11;
            int r  = i & 2047;
            int jj = r >> 7;
            int q  = r & 127;
            *(float4*)(sW + m * NJ * WPAD + jj * WPAD + q * 4) = wtmp[u];
        }
    }
    float bias0, bias1;
    {
        int jb = layer * Hn + j0;
        bias0 = b_ih[jb + J0] + b_hh[jb + J0];
        bias1 = b_ih[jb + J1] + b_hh[jb + J1];
    }
    __syncthreads();

    const unsigned long long biasP0 = (unsigned long long)__float_as_uint(bias0);
    const unsigned long long biasP1 = (unsigned long long)__float_as_uint(bias1);

    for (int t = 0; t < SEQn; ++t) {
        // ---- Wait: own layer step t-1, and layer-1 step t (release/acquire) ----
        if (tid == 0) {
            volatile int* vc = g_cnt;
            if (t > 0) {
                int s = 0;
                while (vc[layer * SEQn + t - 1] < NBC) {
                    __nanosleep(40);
                    if (++s > 1000000) break;
                }
            }
            if (layer > 0) {
                int s = 0;
                while (vc[(layer - 1) * SEQn + t] < NBC) {
                    __nanosleep(40);
                    if (++s > 1000000) break;
                }
            }
            __threadfence();
        }
        __syncthreads();

        const float* inpA = (layer == 0)
            ? (x + (size_t)t * Bn * Hn)
            : (states + (size_t)(t * Ln + (layer - 1)) * Bn * Hn);
        const float* hA =
            states + (size_t)((t - 1) * Ln + layer) * Bn * Hn;  // unused at t==0

        // h(-1)=0: the Whh chunks contribute nothing at t==0 -> skip them.
        const int ncc = (t == 0) ? 4 : 8;

        // 8 independent accumulator chains: {B0,B1}x{J0,J1}x{k-pair parity}
        unsigned long long a00x = biasP0, a00y = 0ull;
        unsigned long long a01x = biasP1, a01y = 0ull;
        unsigned long long a10x = biasP0, a10y = 0ull;
        unsigned long long a11x = biasP1, a11y = 0ull;

        // Chunk-0 prefetch: 2048 float4 per chunk; 8 per thread, coalesced.
        // .cg: bypass (possibly stale, never useful) L1.
        float4 pf[8];
        #pragma unroll
        for (int u = 0; u < 8; ++u) {
            int f4 = u * NTHR + tid;          // row = f4>>5, col4 = f4&31
            pf[u] = ld_cg_f4(inpA + (f4 >> 5) * Hn + (f4 & 31) * 4);
        }
        #pragma unroll
        for (int u = 0; u < 8; ++u) {
            int f4 = u * NTHR + tid;
            *(float4*)(sA0 + (f4 >> 5) * APAD + (f4 & 31) * 4) = pf[u];  // CF STS.128
        }
        __syncthreads();

        // K-chunks: 0..3 over inp (Wih), 4..7 over h (Whh). Double-buffered:
        // one barrier per chunk; LDG of cc+1 issued before compute of cc.
        for (int cc = 0; cc < ncc; ++cc) {
            const float* bufC = (cc & 1) ? sA1 : sA0;
            float*       bufN = (cc & 1) ? sA0 : sA1;

            if (cc < ncc - 1) {
                const float* Asrc = ((cc + 1) < 4) ? inpA : hA;
                int koff = ((cc + 1) & 3) * KC;
                #pragma unroll
                for (int u = 0; u < 8; ++u) {
                    int f4 = u * NTHR + tid;
                    pf[u] = ld_cg_f4(Asrc + (f4 >> 5) * Hn + koff + (f4 & 31) * 4);
                }
            }

            const float* aR0 = bufC + B0 * APAD;
            const float* aR1 = bufC + B1 * APAD;
            const float* wBase = sW + (cc >> 2) * (NJ * WPAD) + (cc & 3) * KC;
            const float* wR0 = wBase + J0 * WPAD;
            const float* wR1 = wBase + J1 * WPAD;

            #pragma unroll 8
            for (int kk = 0; kk < KC; kk += 4) {
                // Each ulonglong2 = two packed f32x2 covering 4 consecutive k.
                ulonglong2 A0 = *(const ulonglong2*)(aR0 + kk);  // 8 addrs/warp, CF
                ulonglong2 A1 = *(const ulonglong2*)(aR1 + kk);
                ulonglong2 W0 = *(const ulonglong2*)(wR0 + kk);  // 4 addrs/warp, CF
                ulonglong2 W1 = *(const ulonglong2*)(wR1 + kk);
                FMA2(a00x, A0.x, W0.x); FMA2(a00y, A0.y, W0.y);
                FMA2(a01x, A0.x, W1.x); FMA2(a01y, A0.y, W1.y);
                FMA2(a10x, A1.x, W0.x); FMA2(a10y, A1.y, W0.y);
                FMA2(a11x, A1.x, W1.x); FMA2(a11y, A1.y, W1.y);
            }

            if (cc < ncc - 1) {      // stage next chunk into the other buffer
                #pragma unroll
                for (int u = 0; u < 8; ++u) {
                    int f4 = u * NTHR + tid;
                    *(float4*)(bufN + (f4 >> 5) * APAD + (f4 & 31) * 4) = pf[u];
                }
            }
            __syncthreads();
        }

        // Horizontal reduce + activation + writeback (.cg stores: straight to L2)
        float r00 = tanhf(hsum2(a00x) + hsum2(a00y));
        float r01 = tanhf(hsum2(a01x) + hsum2(a01y));
        float r10 = tanhf(hsum2(a10x) + hsum2(a10y));
        float r11 = tanhf(hsum2(a11x) + hsum2(a11y));
        {
            float* s0 = states + ((size_t)(t * Ln + layer) * Bn + B0) * Hn + j0;
            float* s1 = states + ((size_t)(t * Ln + layer) * Bn + B1) * Hn + j0;
            st_cg_f32(s0 + J0, r00);
            st_cg_f32(s0 + J1, r01);
            st_cg_f32(s1 + J0, r10);
            st_cg_f32(s1 + J1, r11);
            if (layer == Ln - 1) {
                float* o0 = outputs + ((size_t)t * Bn + B0) * Hn + j0;
                float* o1 = outputs + ((size_t)t * Bn + B1) * Hn + j0;
                st_cg_f32(o0 + J0, r00);
                st_cg_f32(o0 + J1, r01);
                st_cg_f32(o1 + J0, r10);
                st_cg_f32(o1 + J1, r11);
            }
        }

        // Publish: per-thread release fence, barrier, one arrival per block
        __threadfence();
        __syncthreads();
        if (tid == 0) atomicAdd(&g_cnt[layer * SEQn + t], 1);
    }
}

extern "C" void kernel_launch(void* const* d_in, const int* in_sizes, int n_in,
                              void* d_out, int out_size) {
    const float* x    = (const float*)d_in[0];   // [SEQ,B,H]
    const float* w_ih = (const float*)d_in[1];   // [L,H,H]
    const float* b_ih = (const float*)d_in[2];   // [L,H]
    const float* w_hh = (const float*)d_in[3];   // [L,H,H]
    const float* b_hh = (const float*)d_in[4];   // [L,H]
    float* out = (float*)d_out;                  // [SEQ,B,H] outputs ++ [SEQ*L,B,H] states

    cudaFuncSetAttribute(rnn_kernel,
                         cudaFuncAttributeMaxDynamicSharedMemorySize, SMEM_BYTES);

    zero_cnt_kernel<<<1, Ln * SEQn>>>();
    rnn_kernel<<<Ln * NBC, NTHR, SMEM_BYTES>>>(x, w_ih, b_ih, w_hh, b_hh, out);
}

// round 10
// speedup vs baseline: 1.2686x; 1.0058x over previous
#include <cuda_runtime.h>
#include <cuda_bf16.h>

// Problem constants
#define SEQn 256
#define Bn   64
#define Hn   512
#define Ln   4

#define NJ    16      // output columns per block
#define NBC   32      // blocks per layer (NBC*NJ == Hn)
#define NTHR  512     // two 256-thread groups: g0 = Wih GEMM, g1 = Whh GEMM
#define KC    128     // K-chunk staged in shared

#define WPAD  516     // padded W row stride (floats): %32==4, %4==0 -> CF LDS.128
#define APAD  132     // padded A row stride (floats): %32==4, %4==0 -> CF LDS.128

// Dynamic smem: W tiles [2][NJ][WPAD] + per-group double-buffered A [2][2][Bn][APAD]
// + reduction buffer [256][4]
#define SW_FLOATS   (2 * NJ * WPAD)
#define SA_FLOATS   (Bn * APAD)
#define RED_FLOATS  (256 * 4)
#define SMEM_FLOATS (SW_FLOATS + 4 * SA_FLOATS + RED_FLOATS)
#define SMEM_BYTES  (SMEM_FLOATS * 4)   // 205,312 B < 227 KB

// Packed dual-fp32 FMA (sm_100+): d = a * w + d, elementwise on {lo,hi}
#define FMA2(d, a, w) \
    asm("fma.rn.f32x2 %0, %1, %2, %3;" : "=l"(d) : "l"(a), "l"(w), "l"(d))

// Per-group named barrier (256 threads). Group g uses id 1+g; id 0 = __syncthreads.
#define GBAR(id) asm volatile("bar.sync %0, 256;" :: "r"(id) : "memory")

// .cg (L2-only) accessors for the cross-SM-shared activation buffer.
// L1 is NOT coherent across SMs and persists for the whole persistent kernel,
// so any L1 hit on another block's write would be stale. Zero L1 reuse anyway.
__device__ __forceinline__ float4 ld_cg_f4(const float* p) {
    float4 v;
    asm volatile("ld.global.cg.v4.f32 {%0,%1,%2,%3}, [%4];"
                 : "=f"(v.x), "=f"(v.y), "=f"(v.z), "=f"(v.w)
                 : "l"(p));
    return v;
}
__device__ __forceinline__ void st_cg_f32(float* p, float v) {
    asm volatile("st.global.cg.f32 [%0], %1;" :: "l"(p), "f"(v) : "memory");
}

// Persistent device state: per-(layer,t) completion counters, zeroed by a
// prologue kernel on every launch (graph-replay safe). Only 4 KB static.
__device__ int g_cnt[Ln * SEQn];

__global__ void zero_cnt_kernel() {
    g_cnt[threadIdx.x] = 0;   // launched with exactly Ln*SEQn = 1024 threads
}

__device__ __forceinline__ float hsum2(unsigned long long v) {
    float lo = __uint_as_float((unsigned int)(v & 0xffffffffull));
    float hi = __uint_as_float((unsigned int)(v >> 32));
    return lo + hi;
}

__global__ __launch_bounds__(NTHR, 1)
void rnn_kernel(const float* __restrict__ x,
                const float* __restrict__ w_ih,
                const float* __restrict__ b_ih,
                const float* __restrict__ w_hh,
                const float* __restrict__ b_hh,
                float* __restrict__ out)
{
    const int layer = blockIdx.x >> 5;   // /NBC
    const int cb    = blockIdx.x & (NBC - 1);
    const int j0    = cb * NJ;
    const int tid   = threadIdx.x;
    const int g     = tid >> 8;          // 0: inp-side (Wih), 1: h-side (Whh)
    const int tg    = tid & 255;

    // R5 lane tiling within each 256-thread group
    const int lane = tg & 31;
    const int wgid = tg >> 5;            // 0..7 within group
    const int jl   = lane & 3;           // 4 j-lanes
    const int bl   = lane >> 2;          // 8 b-lanes
    const int wb   = wgid & 3;           // 4 b-tiles of 16
    const int wj   = wgid >> 2;          // 2 j-tiles of 8

    const int B0 = wb * 16 + bl;         // thread's two batch rows
    const int B1 = B0 + 8;
    const int J0 = wj * 8 + jl;          // thread's two local cols (within NJ)
    const int J1 = J0 + 4;

    extern __shared__ float smem_dyn[];
    float* sW   = smem_dyn;                                  // [2][NJ][WPAD]
    float* sAg  = smem_dyn + SW_FLOATS + g * 2 * SA_FLOATS;  // this group's 2 buffers
    float* sRed = smem_dyn + SW_FLOATS + 4 * SA_FLOATS;      // [256][4]

    float* outputs = out;                     // [SEQ][B][H]
    float* states  = out + SEQn * Bn * Hn;    // [SEQ][L][B][H]

    // ---- One-time: this group's weight matrix into its padded shared tile ----
    {
        const float* src = (g == 0) ? w_ih : w_hh;
        float4 wtmp[8];    // NJ rows * 128 float4 = 2048; 8 per thread per group
        #pragma unroll
        for (int u = 0; u < 8; ++u) {
            int i  = u * 256 + tg;
            int jj = i >> 7;                  // row within tile
            int q  = i & 127;                 // float4 index within row
            wtmp[u] = ((const float4*)src)[(size_t)(layer * Hn + j0 + jj) * (Hn / 4) + q];
        }
        #pragma unroll
        for (int u = 0; u < 8; ++u) {
            int i  = u * 256 + tg;
            int jj = i >> 7;
            int q  = i & 127;
            *(float4*)(sW + g * NJ * WPAD + jj * WPAD + q * 4) = wtmp[u];
        }
    }
    unsigned long long biasP0 = 0ull, biasP1 = 0ull;
    if (g == 0) {   // bias added once, on the inp side
        int jb = layer * Hn + j0;
        biasP0 = (unsigned long long)__float_as_uint(b_ih[jb + J0] + b_hh[jb + J0]);
        biasP1 = (unsigned long long)__float_as_uint(b_ih[jb + J1] + b_hh[jb + J1]);
    }
    __syncthreads();

    const int gbid = 1 + g;   // named barrier id for this group

    for (int t = 0; t < SEQn; ++t) {
        // Group 0 consumes (layer-1, t); group 1 consumes (layer, t-1).
        const bool active = (g == 0) || (t > 0);

        float p0 = 0.f, p1 = 0.f, p2 = 0.f, p3 = 0.f;

        if (active) {
            // ---- Group-local dependency wait (release/acquire via L2) ----
            const bool needwait = (g == 0) ? (layer > 0) : true;
            if (needwait) {
                if (tg == 0) {
                    const int cidx = (g == 0) ? ((layer - 1) * SEQn + t)
                                              : (layer * SEQn + (t - 1));
                    volatile int* vc = g_cnt;
                    int s = 0;
                    while (vc[cidx] < NBC) {
                        __nanosleep(40);
                        if (++s > 1000000) break;
                    }
                    __threadfence();
                }
                GBAR(gbid);
            }

            const float* Asrc = (g == 0)
                ? ((layer == 0)
                       ? (x + (size_t)t * Bn * Hn)
                       : (states + (size_t)(t * Ln + (layer - 1)) * Bn * Hn))
                : (states + (size_t)((t - 1) * Ln + layer) * Bn * Hn);

            // 8 independent accumulator chains: {B0,B1}x{J0,J1}x{k-pair parity}
            unsigned long long a00x = biasP0, a00y = 0ull;
            unsigned long long a01x = biasP1, a01y = 0ull;
            unsigned long long a10x = biasP0, a10y = 0ull;
            unsigned long long a11x = biasP1, a11y = 0ull;

            // Chunk-0 prefetch: 2048 float4 per chunk; 8 per thread, coalesced .cg
            float4 pf[8];
            #pragma unroll
            for (int u = 0; u < 8; ++u) {
                int f4 = u * 256 + tg;         // row = f4>>5, col4 = f4&31
                pf[u] = ld_cg_f4(Asrc + (f4 >> 5) * Hn + (f4 & 31) * 4);
            }
            #pragma unroll
            for (int u = 0; u < 8; ++u) {
                int f4 = u * 256 + tg;
                *(float4*)(sAg + (f4 >> 5) * APAD + (f4 & 31) * 4) = pf[u];  // CF STS.128
            }
            GBAR(gbid);

            // 4 K-chunks over this group's 512-wide K range. Double-buffered:
            // one group barrier per chunk; LDG of cc+1 issued before compute of cc.
            for (int cc = 0; cc < 4; ++cc) {
                const float* bufC = sAg + (cc & 1) * SA_FLOATS;
                float*       bufN = sAg + ((cc & 1) ^ 1) * SA_FLOATS;

                if (cc < 3) {
                    int koff = (cc + 1) * KC;
                    #pragma unroll
                    for (int u = 0; u < 8; ++u) {
                        int f4 = u * 256 + tg;
                        pf[u] = ld_cg_f4(Asrc + (f4 >> 5) * Hn + koff + (f4 & 31) * 4);
                    }
                }

                const float* aR0 = bufC + B0 * APAD;
                const float* aR1 = bufC + B1 * APAD;
                const float* wBase = sW + g * (NJ * WPAD) + cc * KC;
                const float* wR0 = wBase + J0 * WPAD;
                const float* wR1 = wBase + J1 * WPAD;

                #pragma unroll 8
                for (int kk = 0; kk < KC; kk += 4) {
                    // Each ulonglong2 = two packed f32x2 covering 4 consecutive k.
                    ulonglong2 A0 = *(const ulonglong2*)(aR0 + kk);  // 8 addrs/warp, CF
                    ulonglong2 A1 = *(const ulonglong2*)(aR1 + kk);
                    ulonglong2 W0 = *(const ulonglong2*)(wR0 + kk);  // 4 addrs/warp, CF
                    ulonglong2 W1 = *(const ulonglong2*)(wR1 + kk);
                    FMA2(a00x, A0.x, W0.x); FMA2(a00y, A0.y, W0.y);
                    FMA2(a01x, A0.x, W1.x); FMA2(a01y, A0.y, W1.y);
                    FMA2(a10x, A1.x, W0.x); FMA2(a10y, A1.y, W0.y);
                    FMA2(a11x, A1.x, W1.x); FMA2(a11y, A1.y, W1.y);
                }

                if (cc < 3) {      // stage next chunk into the other buffer
                    #pragma unroll
                    for (int u = 0; u < 8; ++u) {
                        int f4 = u * 256 + tg;
                        *(float4*)(bufN + (f4 >> 5) * APAD + (f4 & 31) * 4) = pf[u];
                    }
                }
                GBAR(gbid);
            }

            p0 = hsum2(a00x) + hsum2(a00y);
            p1 = hsum2(a01x) + hsum2(a01y);
            p2 = hsum2(a10x) + hsum2(a10y);
            p3 = hsum2(a11x) + hsum2(a11y);
        }

        // ---- Join: g1 publishes partials, g0 finalizes ----
        if (g == 1) {
            float4 v; v.x = p0; v.y = p1; v.z = p2; v.w = p3;
            *(float4*)(sRed + tg * 4) = v;
        }
        __syncthreads();

        if (g == 0) {
            float4 q = *(const float4*)(sRed + tg * 4);
            float r00 = tanhf(p0 + q.x);
            float r01 = tanhf(p1 + q.y);
            float r10 = tanhf(p2 + q.z);
            float r11 = tanhf(p3 + q.w);

            float* s0 = states + ((size_t)(t * Ln + layer) * Bn + B0) * Hn + j0;
            float* s1 = states + ((size_t)(t * Ln + layer) * Bn + B1) * Hn + j0;
            st_cg_f32(s0 + J0, r00);
            st_cg_f32(s0 + J1, r01);
            st_cg_f32(s1 + J0, r10);
            st_cg_f32(s1 + J1, r11);
            if (layer == Ln - 1) {
                float* o0 = outputs + ((size_t)t * Bn + B0) * Hn + j0;
                float* o1 = outputs + ((size_t)t * Bn + B1) * Hn + j0;
                st_cg_f32(o0 + J0, r00);
                st_cg_f32(o0 + J1, r01);
                st_cg_f32(o1 + J0, r10);
                st_cg_f32(o1 + J1, r11);
            }
        }

        // Publish: per-thread release fence, barrier, one arrival per block
        __threadfence();
        __syncthreads();
        if (tid == 0) atomicAdd(&g_cnt[layer * SEQn + t], 1);
    }
}

extern "C" void kernel_launch(void* const* d_in, const int* in_sizes, int n_in,
                              void* d_out, int out_size) {
    const float* x    = (const float*)d_in[0];   // [SEQ,B,H]
    const float* w_ih = (const float*)d_in[1];   // [L,H,H]
    const float* b_ih = (const float*)d_in[2];   // [L,H]
    const float* w_hh = (const float*)d_in[3];   // [L,H,H]
    const float* b_hh = (const float*)d_in[4];   // [L,H]
    float* out = (float*)d_out;                  // [SEQ,B,H] outputs ++ [SEQ*L,B,H] states

    cudaFuncSetAttribute(rnn_kernel,
                         cudaFuncAttributeMaxDynamicSharedMemorySize, SMEM_BYTES);

    zero_cnt_kernel<<<1, Ln * SEQn>>>();
    rnn_kernel<<<Ln * NBC, NTHR, SMEM_BYTES>>>(x, w_ih, b_ih, w_hh, b_hh, out);
}

// round 11
// speedup vs baseline: 1.3934x; 1.0984x over previous
#include <cuda_runtime.h>
#include <cuda_bf16.h>

// Problem constants
#define SEQn 256
#define Bn   64
#define Hn   512
#define Ln   4

#define NJ    16      // output columns per block
#define NBC   32      // blocks per layer (NBC*NJ == Hn)
#define NTHR  256     // 8 warps
#define KC    128     // K-chunk staged in shared

// Slice-padded layouts (floats). SS=36: 32 data + 4 pad, SS/4=9 (odd mod 8).
// AR=148: A row stride, AR/4=37 odd -> quarter-warp CF for the 4b x 4ks loads.
// WROW=576 = 16 slices * 36.
#define SS    36
#define AR    148
#define WROW  576
#define WMAT  (16 * WROW)          // 9216 floats per weight matrix tile

#define SW_FLOATS   (2 * WMAT)     // 18432
#define SA_FLOATS   (Bn * AR)      // 9472
#define SMEM_FLOATS (SW_FLOATS + 2 * SA_FLOATS)
#define SMEM_BYTES  (SMEM_FLOATS * 4)   // 149,504 B

// Packed dual-fp32 FMA (sm_100+): d = a * w + d, elementwise on {lo,hi}
#define FMA2(d, a, w) \
    asm("fma.rn.f32x2 %0, %1, %2, %3;" : "=l"(d) : "l"(a), "l"(w), "l"(d))

// .cg (L2-only) accessors for the cross-SM-shared activation buffer.
// L1 is NOT coherent across SMs and persists for the whole persistent kernel,
// so any L1 hit on another block's write would be stale. Zero L1 reuse anyway.
__device__ __forceinline__ float4 ld_cg_f4(const float* p) {
    float4 v;
    asm volatile("ld.global.cg.v4.f32 {%0,%1,%2,%3}, [%4];"
                 : "=f"(v.x), "=f"(v.y), "=f"(v.z), "=f"(v.w)
                 : "l"(p));
    return v;
}
__device__ __forceinline__ void st_cg_f4(float* p, float4 v) {
    asm volatile("st.global.cg.v4.f32 [%0], {%1,%2,%3,%4};"
                 :: "l"(p), "f"(v.x), "f"(v.y), "f"(v.z), "f"(v.w) : "memory");
}

// Persistent device state: per-(layer,t) completion counters, zeroed by a
// prologue kernel on every launch (graph-replay safe). Only 4 KB static.
__device__ int g_cnt[Ln * SEQn];

__global__ void zero_cnt_kernel() {
    g_cnt[threadIdx.x] = 0;   // launched with exactly Ln*SEQn = 1024 threads
}

__device__ __forceinline__ float hsum2(unsigned long long v) {
    float lo = __uint_as_float((unsigned int)(v & 0xffffffffull));
    float hi = __uint_as_float((unsigned int)(v >> 32));
    return lo + hi;
}

__global__ __launch_bounds__(NTHR, 1)
void rnn_kernel(const float* __restrict__ x,
                const float* __restrict__ w_ih,
                const float* __restrict__ b_ih,
                const float* __restrict__ w_hh,
                const float* __restrict__ b_hh,
                float* __restrict__ out)
{
    const int layer = blockIdx.x >> 5;   // /NBC
    const int cb    = blockIdx.x & (NBC - 1);
    const int j0    = cb * NJ;
    const int tid   = threadIdx.x;

    // Mapping: warp = jt*2 + bhi ; lane = btl*4 + ks
    // Thread tile: 4 rows (b = bt*4 .. +3) x 4 cols (j = jt*4 .. +3),
    // over k-slice ks (32 of each 128-K chunk). Split-K x4, shuffle-reduced.
    const int lane = tid & 31;
    const int w    = tid >> 5;
    const int jt   = w >> 1;             // 0..3
    const int bhi  = w & 1;              // 0..1
    const int btl  = lane >> 2;          // 0..7
    const int ks   = lane & 3;           // 0..3 k-slice
    const int bt   = bhi * 8 + btl;      // 0..15

    extern __shared__ float smem_dyn[];
    float* sW  = smem_dyn;                          // [2][16][WROW] slice-padded
    float* sA0 = smem_dyn + SW_FLOATS;              // A buffer 0 [64][AR]
    float* sA1 = smem_dyn + SW_FLOATS + SA_FLOATS;  // A buffer 1

    float* outputs = out;                     // [SEQ][B][H]
    float* states  = out + SEQn * Bn * Hn;    // [SEQ][L][B][H]

    // ---- One-time: weights into slice-padded shared tiles ----
    {
        float4 wtmp[16];   // 2 mats * 16 rows * 128 f4 = 4096; 16/thread
        #pragma unroll
        for (int u = 0; u < 16; ++u) {
            int i = u * NTHR + tid;
            int m = i >> 11;               // 0: ih, 1: hh
            int r = i & 2047;
            int j = r >> 7;                // row within tile
            int q = r & 127;               // f4 index within 512-float row
            const float* src = (m ? w_hh : w_ih);
            wtmp[u] = ((const float4*)src)[(size_t)(layer * Hn + j0 + j) * (Hn / 4) + q];
        }
        #pragma unroll
        for (int u = 0; u < 16; ++u) {
            int i = u * NTHR + tid;
            int m = i >> 11;
            int r = i & 2047;
            int j = r >> 7;
            int q = r & 127;
            // f4 addr: mat + row + slice(q>>3)*9 + within-slice(q&7)
            ((float4*)sW)[m * (WMAT / 4) + j * (WROW / 4) + (q >> 3) * (SS / 4) + (q & 7)] = wtmp[u];
        }
    }
    float bias0, bias1, bias2, bias3;
    {
        int jb = layer * Hn + j0 + jt * 4;
        bias0 = b_ih[jb + 0] + b_hh[jb + 0];
        bias1 = b_ih[jb + 1] + b_hh[jb + 1];
        bias2 = b_ih[jb + 2] + b_hh[jb + 2];
        bias3 = b_ih[jb + 3] + b_hh[jb + 3];
    }
    __syncthreads();

    for (int t = 0; t < SEQn; ++t) {
        // ---- Wait: own layer step t-1, and layer-1 step t (release/acquire) ----
        if (tid == 0) {
            volatile int* vc = g_cnt;
            if (t > 0) {
                int s = 0;
                while (vc[layer * SEQn + t - 1] < NBC) {
                    __nanosleep(40);
                    if (++s > 1000000) break;
                }
            }
            if (layer > 0) {
                int s = 0;
                while (vc[(layer - 1) * SEQn + t] < NBC) {
                    __nanosleep(40);
                    if (++s > 1000000) break;
                }
            }
            __threadfence();
        }
        __syncthreads();

        const float* inpA = (layer == 0)
            ? (x + (size_t)t * Bn * Hn)
            : (states + (size_t)(t * Ln + (layer - 1)) * Bn * Hn);
        const float* hA =
            states + (size_t)((t - 1) * Ln + layer) * Bn * Hn;  // unused at t==0

        // h(-1)=0: skip the Whh chunks at t==0.
        const int ncc = (t == 0) ? 4 : 8;

        // 16 packed accumulator chains: acc[i][jj], i=row-in-tile, jj=col-in-tile
        unsigned long long a00=0,a01=0,a02=0,a03=0;
        unsigned long long a10=0,a11=0,a12=0,a13=0;
        unsigned long long a20=0,a21=0,a22=0,a23=0;
        unsigned long long a30=0,a31=0,a32=0,a33=0;

        // Chunk-0 prefetch: 2048 f4; 8/thread, coalesced .cg LDG -> padded STS
        float4 pf[8];
        #pragma unroll
        for (int u = 0; u < 8; ++u) {
            int f4 = u * NTHR + tid;           // row = f4>>5, col4 = f4&31
            pf[u] = ld_cg_f4(inpA + (f4 >> 5) * Hn + (f4 & 31) * 4);
        }
        #pragma unroll
        for (int u = 0; u < 8; ++u) {
            int f4 = u * NTHR + tid;
            int row = f4 >> 5, c4 = f4 & 31;
            ((float4*)sA0)[row * (AR / 4) + (c4 >> 3) * (SS / 4) + (c4 & 7)] = pf[u];
        }
        __syncthreads();

        // K-chunks: 0..3 over inp (Wih), 4..7 over h (Whh). Double-buffered.
        for (int cc = 0; cc < ncc; ++cc) {
            const float* bufC = (cc & 1) ? sA1 : sA0;
            float*       bufN = (cc & 1) ? sA0 : sA1;

            if (cc < ncc - 1) {
                const float* Asrc = ((cc + 1) < 4) ? inpA : hA;
                int koff = ((cc + 1) & 3) * KC;
                #pragma unroll
                for (int u = 0; u < 8; ++u) {
                    int f4 = u * NTHR + tid;
                    pf[u] = ld_cg_f4(Asrc + (f4 >> 5) * Hn + koff + (f4 & 31) * 4);
                }
            }

            // This thread's A rows at its k-slice; W rows for its 4 cols.
            const float* aB = bufC + (bt * 4) * AR + ks * SS;
            const float* wB = sW + (cc >> 2) * WMAT + (jt * 4) * WROW
                              + ((cc & 3) * 4 + ks) * SS;

            #pragma unroll 8
            for (int kk = 0; kk < 32; kk += 4) {
                ulonglong2 A0 = *(const ulonglong2*)(aB + 0 * AR + kk);
                ulonglong2 A1 = *(const ulonglong2*)(aB + 1 * AR + kk);
                ulonglong2 A2 = *(const ulonglong2*)(aB + 2 * AR + kk);
                ulonglong2 A3 = *(const ulonglong2*)(aB + 3 * AR + kk);
                ulonglong2 W0 = *(const ulonglong2*)(wB + 0 * WROW + kk);
                ulonglong2 W1 = *(const ulonglong2*)(wB + 1 * WROW + kk);
                ulonglong2 W2 = *(const ulonglong2*)(wB + 2 * WROW + kk);
                ulonglong2 W3 = *(const ulonglong2*)(wB + 3 * WROW + kk);
                FMA2(a00, A0.x, W0.x); FMA2(a00, A0.y, W0.y);
                FMA2(a01, A0.x, W1.x); FMA2(a01, A0.y, W1.y);
                FMA2(a02, A0.x, W2.x); FMA2(a02, A0.y, W2.y);
                FMA2(a03, A0.x, W3.x); FMA2(a03, A0.y, W3.y);
                FMA2(a10, A1.x, W0.x); FMA2(a10, A1.y, W0.y);
                FMA2(a11, A1.x, W1.x); FMA2(a11, A1.y, W1.y);
                FMA2(a12, A1.x, W2.x); FMA2(a12, A1.y, W2.y);
                FMA2(a13, A1.x, W3.x); FMA2(a13, A1.y, W3.y);
                FMA2(a20, A2.x, W0.x); FMA2(a20, A2.y, W0.y);
                FMA2(a21, A2.x, W1.x); FMA2(a21, A2.y, W1.y);
                FMA2(a22, A2.x, W2.x); FMA2(a22, A2.y, W2.y);
                FMA2(a23, A2.x, W3.x); FMA2(a23, A2.y, W3.y);
                FMA2(a30, A3.x, W0.x); FMA2(a30, A3.y, W0.y);
                FMA2(a31, A3.x, W1.x); FMA2(a31, A3.y, W1.y);
                FMA2(a32, A3.x, W2.x); FMA2(a32, A3.y, W2.y);
                FMA2(a33, A3.x, W3.x); FMA2(a33, A3.y, W3.y);
            }

            if (cc < ncc - 1) {      // stage next chunk into the other buffer
                #pragma unroll
                for (int u = 0; u < 8; ++u) {
                    int f4 = u * NTHR + tid;
                    int row = f4 >> 5, c4 = f4 & 31;
                    ((float4*)bufN)[row * (AR / 4) + (c4 >> 3) * (SS / 4) + (c4 & 7)] = pf[u];
                }
            }
            __syncthreads();
        }

        // ---- Split-K reduce: 4 ks lanes of same (bt,jt) are lane^1, lane^2 ----
        float r00=hsum2(a00), r01=hsum2(a01), r02=hsum2(a02), r03=hsum2(a03);
        float r10=hsum2(a10), r11=hsum2(a11), r12=hsum2(a12), r13=hsum2(a13);
        float r20=hsum2(a20), r21=hsum2(a21), r22=hsum2(a22), r23=hsum2(a23);
        float r30=hsum2(a30), r31=hsum2(a31), r32=hsum2(a32), r33=hsum2(a33);
        #pragma unroll
        for (int d = 1; d <= 2; d <<= 1) {
            r00 += __shfl_xor_sync(0xffffffffu, r00, d);
            r01 += __shfl_xor_sync(0xffffffffu, r01, d);
            r02 += __shfl_xor_sync(0xffffffffu, r02, d);
            r03 += __shfl_xor_sync(0xffffffffu, r03, d);
            r10 += __shfl_xor_sync(0xffffffffu, r10, d);
            r11 += __shfl_xor_sync(0xffffffffu, r11, d);
            r12 += __shfl_xor_sync(0xffffffffu, r12, d);
            r13 += __shfl_xor_sync(0xffffffffu, r13, d);
            r20 += __shfl_xor_sync(0xffffffffu, r20, d);
            r21 += __shfl_xor_sync(0xffffffffu, r21, d);
            r22 += __shfl_xor_sync(0xffffffffu, r22, d);
            r23 += __shfl_xor_sync(0xffffffffu, r23, d);
            r30 += __shfl_xor_sync(0xffffffffu, r30, d);
            r31 += __shfl_xor_sync(0xffffffffu, r31, d);
            r32 += __shfl_xor_sync(0xffffffffu, r32, d);
            r33 += __shfl_xor_sync(0xffffffffu, r33, d);
        }

        // Lane ks finalizes row i==ks of the 4x4 tile.
        float o0, o1, o2, o3;
        if      (ks == 0) { o0 = r00; o1 = r01; o2 = r02; o3 = r03; }
        else if (ks == 1) { o0 = r10; o1 = r11; o2 = r12; o3 = r13; }
        else if (ks == 2) { o0 = r20; o1 = r21; o2 = r22; o3 = r23; }
        else              { o0 = r30; o1 = r31; o2 = r32; o3 = r33; }
        float4 v;
        v.x = tanhf(o0 + bias0);
        v.y = tanhf(o1 + bias1);
        v.z = tanhf(o2 + bias2);
        v.w = tanhf(o3 + bias3);

        {
            int brow = bt * 4 + ks;
            float* sp = states + ((size_t)(t * Ln + layer) * Bn + brow) * Hn
                        + j0 + jt * 4;
            st_cg_f4(sp, v);
            if (layer == Ln - 1) {
                float* op = outputs + ((size_t)t * Bn + brow) * Hn + j0 + jt * 4;
                st_cg_f4(op, v);
            }
        }

        // Publish: per-thread release fence, barrier, one arrival per block
        __threadfence();
        __syncthreads();
        if (tid == 0) atomicAdd(&g_cnt[layer * SEQn + t], 1);
    }
}

extern "C" void kernel_launch(void* const* d_in, const int* in_sizes, int n_in,
                              void* d_out, int out_size) {
    const float* x    = (const float*)d_in[0];   // [SEQ,B,H]
    const float* w_ih = (const float*)d_in[1];   // [L,H,H]
    const float* b_ih = (const float*)d_in[2];   // [L,H]
    const float* w_hh = (const float*)d_in[3];   // [L,H,H]
    const float* b_hh = (const float*)d_in[4];   // [L,H]
    float* out = (float*)d_out;                  // [SEQ,B,H] outputs ++ [SEQ*L,B,H] states

    cudaFuncSetAttribute(rnn_kernel,
                         cudaFuncAttributeMaxDynamicSharedMemorySize, SMEM_BYTES);

    zero_cnt_kernel<<<1, Ln * SEQn>>>();
    rnn_kernel<<<Ln * NBC, NTHR, SMEM_BYTES>>>(x, w_ih, b_ih, w_hh, b_hh, out);
}

// round 12
// speedup vs baseline: 1.4451x; 1.0370x over previous
#include <cuda_runtime.h>
#include <cuda_bf16.h>

// Problem constants
#define SEQn 256
#define Bn   64
#define Hn   512
#define Ln   4

#define NJ    16      // output columns per block
#define NBC   32      // blocks per layer (NBC*NJ == Hn)
#define NTHR  512     // 16 warps, 4 per SMSP
#define KC    128     // K-chunk staged in shared

#define WPAD  516     // W row stride (floats): %32==4, 16B-mult -> CF
#define APAD  132     // A row stride (floats): %32==4, 16B-mult -> CF
#define WMAT  (NJ * WPAD)

#define SW_FLOATS   (2 * WMAT)     // 16512
#define SA_FLOATS   (Bn * APAD)    // 8448
#define SMEM_FLOATS (SW_FLOATS + 2 * SA_FLOATS)
#define SMEM_BYTES  (SMEM_FLOATS * 4)   // 133,632 B

// Packed dual-fp32 ops (sm_100+)
#define FMA2(d, a, w) \
    asm("fma.rn.f32x2 %0, %1, %2, %3;" : "=l"(d) : "l"(a), "l"(w), "l"(d))
#define ADD2(d, a, b) \
    asm("add.rn.f32x2 %0, %1, %2;" : "=l"(d) : "l"(a), "l"(b))

// .cg (L2-only) accessors for the cross-SM-shared activation buffer.
// L1 is NOT coherent across SMs and persists for the persistent kernel.
__device__ __forceinline__ float4 ld_cg_f4(const float* p) {
    float4 v;
    asm volatile("ld.global.cg.v4.f32 {%0,%1,%2,%3}, [%4];"
                 : "=f"(v.x), "=f"(v.y), "=f"(v.z), "=f"(v.w)
                 : "l"(p));
    return v;
}
__device__ __forceinline__ void st_cg_f2(float* p, float a, float b) {
    asm volatile("st.global.cg.v2.f32 [%0], {%1,%2};"
                 :: "l"(p), "f"(a), "f"(b) : "memory");
}

__device__ __forceinline__ unsigned long long shfl_xor_u64(unsigned long long v, int d) {
    unsigned lo = (unsigned)v, hi = (unsigned)(v >> 32);
    lo = __shfl_xor_sync(0xffffffffu, lo, d);
    hi = __shfl_xor_sync(0xffffffffu, hi, d);
    return ((unsigned long long)hi << 32) | lo;
}

__device__ __forceinline__ float hsum2(unsigned long long v) {
    float lo = __uint_as_float((unsigned int)(v & 0xffffffffull));
    float hi = __uint_as_float((unsigned int)(v >> 32));
    return lo + hi;
}

// Persistent state: per-(layer,t) counters, zeroed each launch (graph-safe).
__device__ int g_cnt[Ln * SEQn];

__global__ void zero_cnt_kernel() {
    g_cnt[threadIdx.x] = 0;   // launched with exactly Ln*SEQn = 1024 threads
}

__global__ __launch_bounds__(NTHR, 1)
void rnn_kernel(const float* __restrict__ x,
                const float* __restrict__ w_ih,
                const float* __restrict__ b_ih,
                const float* __restrict__ w_hh,
                const float* __restrict__ b_hh,
                float* __restrict__ out)
{
    const int layer = blockIdx.x >> 5;   // /NBC
    const int cb    = blockIdx.x & (NBC - 1);
    const int j0    = cb * NJ;
    const int tid   = threadIdx.x;

    // Tiling: 32 positions (8 b-tiles x 4 j-tiles) x 16 k-slices.
    // pos = wid*2 + (lane>>4); bt = pos>>2 = wid>>1; jt = pos&3.
    const int lane = tid & 31;
    const int wid  = tid >> 5;
    const int ks   = lane & 15;                      // k-slice 0..15
    const int bt   = wid >> 1;                       // 0..7 (8 rows each)
    const int jt   = ((wid & 1) << 1) | (lane >> 4); // 0..3 (4 cols each)

    // Bit-reversed ks -> which 2 outputs this lane owns after the butterfly.
    const int R = ((ks & 1) << 3) | ((ks & 2) << 1) | ((ks & 4) >> 1) | ((ks & 8) >> 3);
    const int brow = bt * 8 + (R >> 1);              // batch row of my outputs
    const int jloc = jt * 4 + 2 * (R & 1);           // first of 2 consecutive j

    extern __shared__ float smem_dyn[];
    float* sW  = smem_dyn;                          // [2][NJ][WPAD]: ih then hh
    float* sA0 = smem_dyn + SW_FLOATS;              // A buffer 0 [64][APAD]
    float* sA1 = smem_dyn + SW_FLOATS + SA_FLOATS;  // A buffer 1

    float* outputs = out;                     // [SEQ][B][H]
    float* states  = out + SEQn * Bn * Hn;    // [SEQ][L][B][H]

    // ---- One-time: weights into padded shared tiles (reused for all 256 t) ----
    {
        float4 wtmp[8];    // 2 mats * NJ rows * 128 f4 = 4096; 8/thread
        #pragma unroll
        for (int u = 0; u < 8; ++u) {
            int i = u * NTHR + tid;
            int m = i >> 11;               // 0: ih, 1: hh
            int r = i & 2047;
            int j = r >> 7;                // row within tile
            int q = r & 127;               // f4 index within 512-float row
            const float* src = (m ? w_hh : w_ih);
            wtmp[u] = ((const float4*)src)[(size_t)(layer * Hn + j0 + j) * (Hn / 4) + q];
        }
        #pragma unroll
        for (int u = 0; u < 8; ++u) {
            int i = u * NTHR + tid;
            int m = i >> 11;
            int r = i & 2047;
            int j = r >> 7;
            int q = r & 127;
            *(float4*)(sW + m * WMAT + j * WPAD + q * 4) = wtmp[u];
        }
    }
    float bias0, bias1;
    {
        int jb = layer * Hn + j0 + jloc;
        bias0 = b_ih[jb + 0] + b_hh[jb + 0];
        bias1 = b_ih[jb + 1] + b_hh[jb + 1];
    }
    __syncthreads();

    for (int t = 0; t < SEQn; ++t) {
        // ---- Wait: own layer step t-1, and layer-1 step t (release/acquire) ----
        if (tid == 0) {
            volatile int* vc = g_cnt;
            if (t > 0) {
                int s = 0;
                while (vc[layer * SEQn + t - 1] < NBC) {
                    __nanosleep(40);
                    if (++s > 1000000) break;
                }
            }
            if (layer > 0) {
                int s = 0;
                while (vc[(layer - 1) * SEQn + t] < NBC) {
                    __nanosleep(40);
                    if (++s > 1000000) break;
                }
            }
            __threadfence();
        }
        __syncthreads();

        const float* inpA = (layer == 0)
            ? (x + (size_t)t * Bn * Hn)
            : (states + (size_t)(t * Ln + (layer - 1)) * Bn * Hn);
        const float* hA =
            states + (size_t)((t - 1) * Ln + layer) * Bn * Hn;  // unused at t==0

        // h(-1)=0: skip the Whh chunks at t==0.
        const int ncc = (t == 0) ? 4 : 8;

        // 32 packed accumulators: acc[r][w], r = b-row in tile, w = j-col in tile
        unsigned long long acc[8][4];
        #pragma unroll
        for (int r = 0; r < 8; ++r)
            #pragma unroll
            for (int w = 0; w < 4; ++w) acc[r][w] = 0ull;

        // Chunk-0 prefetch: 2048 f4; 4/thread, coalesced .cg LDG
        float4 pf[4];
        #pragma unroll
        for (int u = 0; u < 4; ++u) {
            int f4 = u * NTHR + tid;           // row = f4>>5, c4 = f4&31
            pf[u] = ld_cg_f4(inpA + (f4 >> 5) * Hn + (f4 & 31) * 4);
        }
        #pragma unroll
        for (int u = 0; u < 4; ++u) {
            int f4 = u * NTHR + tid;
            *(float4*)(sA0 + (f4 >> 5) * APAD + (f4 & 31) * 4) = pf[u];  // CF STS
        }
        __syncthreads();

        // K-chunks: 0..3 over inp (Wih), 4..7 over h (Whh). Double-buffered.
        for (int cc = 0; cc < ncc; ++cc) {
            const float* bufC = (cc & 1) ? sA1 : sA0;
            float*       bufN = (cc & 1) ? sA0 : sA1;

            if (cc < ncc - 1) {
                const float* Asrc = ((cc + 1) < 4) ? inpA : hA;
                int koff = ((cc + 1) & 3) * KC;
                #pragma unroll
                for (int u = 0; u < 4; ++u) {
                    int f4 = u * NTHR + tid;
                    pf[u] = ld_cg_f4(Asrc + (f4 >> 5) * Hn + koff + (f4 & 31) * 4);
                }
            }

            // Strided k-slices: k = ks*4 + ii*64 (per-instr quarter-warp stride
            // 4ks mod 32 = {0,4,..,28} -> conflict-free with plain layouts).
            const float* aBase = bufC + ks * 4;
            const float* wBase = sW + (cc >> 2) * WMAT + (jt * 4) * WPAD
                                 + (cc & 3) * KC + ks * 4;

            #pragma unroll
            for (int ii = 0; ii < 2; ++ii) {
                const float* aP = aBase + ii * 64;
                const float* wP = wBase + ii * 64;
                ulonglong2 Ar[8];
                #pragma unroll
                for (int r = 0; r < 8; ++r)
                    Ar[r] = *(const ulonglong2*)(aP + (bt * 8 + r) * APAD);
                ulonglong2 Wr[4];
                #pragma unroll
                for (int w = 0; w < 4; ++w)
                    Wr[w] = *(const ulonglong2*)(wP + w * WPAD);
                #pragma unroll
                for (int r = 0; r < 8; ++r)
                    #pragma unroll
                    for (int w = 0; w < 4; ++w) {
                        FMA2(acc[r][w], Ar[r].x, Wr[w].x);
                        FMA2(acc[r][w], Ar[r].y, Wr[w].y);
                    }
            }

            if (cc < ncc - 1) {      // stage next chunk into the other buffer
                #pragma unroll
                for (int u = 0; u < 4; ++u) {
                    int f4 = u * NTHR + tid;
                    *(float4*)(bufN + (f4 >> 5) * APAD + (f4 & 31) * 4) = pf[u];
                }
            }
            __syncthreads();
        }

        // ---- 16-way split-K reduce: packed shfl butterfly over ks lanes ----
        unsigned long long V[32];
        #pragma unroll
        for (int r = 0; r < 8; ++r)
            #pragma unroll
            for (int w = 0; w < 4; ++w) V[r * 4 + w] = acc[r][w];

        int len = 32;
        #pragma unroll
        for (int d = 1; d <= 8; d <<= 1) {
            len >>= 1;
            const bool hi = (ks & d) != 0;
            #pragma unroll
            for (int i = 0; i < 16; ++i) {
                if (i < len) {
                    unsigned long long send = hi ? V[i] : V[i + len];
                    unsigned long long recv = shfl_xor_u64(send, d);
                    unsigned long long keep = hi ? V[i + len] : V[i];
                    ADD2(V[i], keep, recv);
                }
            }
        }
        // Lane now owns global v = 2*bitrev4(ks) + {0,1} -> (brow, jloc..jloc+1)
        float r0 = tanhf(hsum2(V[0]) + bias0);
        float r1 = tanhf(hsum2(V[1]) + bias1);

        {
            float* sp = states + ((size_t)(t * Ln + layer) * Bn + brow) * Hn
                        + j0 + jloc;
            st_cg_f2(sp, r0, r1);
            if (layer == Ln - 1) {
                float* op = outputs + ((size_t)t * Bn + brow) * Hn + j0 + jloc;
                st_cg_f2(op, r0, r1);
            }
        }

        // Publish: release fence, barrier, one arrival per block
        __threadfence();
        __syncthreads();
        if (tid == 0) atomicAdd(&g_cnt[layer * SEQn + t], 1);
    }
}

extern "C" void kernel_launch(void* const* d_in, const int* in_sizes, int n_in,
                              void* d_out, int out_size) {
    const float* x    = (const float*)d_in[0];   // [SEQ,B,H]
    const float* w_ih = (const float*)d_in[1];   // [L,H,H]
    const float* b_ih = (const float*)d_in[2];   // [L,H]
    const float* w_hh = (const float*)d_in[3];   // [L,H,H]
    const float* b_hh = (const float*)d_in[4];   // [L,H]
    float* out = (float*)d_out;                  // [SEQ,B,H] outputs ++ [SEQ*L,B,H] states

    cudaFuncSetAttribute(rnn_kernel,
                         cudaFuncAttributeMaxDynamicSharedMemorySize, SMEM_BYTES);

    zero_cnt_kernel<<<1, Ln * SEQn>>>();
    rnn_kernel<<<Ln * NBC, NTHR, SMEM_BYTES>>>(x, w_ih, b_ih, w_hh, b_hh, out);
}

// round 14
// speedup vs baseline: 2.3771x; 1.6450x over previous
#include <cuda_runtime.h>
#include <cuda_bf16.h>
#include <cstdint>

// Problem constants
#define SEQn 256
#define Bn   64
#define Hn   512
#define Ln   4
#define NJ   16       // output columns per block
#define NBC  32       // blocks per layer
#define NTHR 256      // 8 warps; warp w owns k-slice [w*16, w*16+16) of each chunk
#define KCH  128      // k per staged chunk
#define NCHUNK 8      // 4 chunks inp + 4 chunks h

// ---- SMEM byte map ----
// W tiles: [16 rows][1024 k] bf16, row stride 2064 (=1024*2+16; 516 words %32==4
//   -> ldmatrix 8-row groups conflict-free). hi then lo.
// A tiles: [2 dbuf][2 hi/lo][64 rows][128 k] bf16, row stride 272 (68 words %32==4).
// Red: 8 warps x [64 m][20 words] fp32 split-K partials.
#define WROWB  2064
#define SM_WHI 0
#define SM_WLO (16 * WROWB)                  // 33,024
#define AROWB  272
#define ATILEB (64 * AROWB)                  // 17,408
#define SM_A   (2 * 16 * WROWB)              // 66,048
#define REDW   20
#define SM_RED (SM_A + 4 * ATILEB)           // 135,680
#define SMEM_BYTES (SM_RED + 8 * 64 * REDW * 4)   // 176,640 B

// ---- PTX helpers (all baseline sm_80+; no arch-feature suffix needed) ----
#define LDSM4(r0, r1, r2, r3, addr) \
    asm volatile("ldmatrix.sync.aligned.m8n8.x4.shared.b16 {%0,%1,%2,%3}, [%4];" \
                 : "=r"(r0), "=r"(r1), "=r"(r2), "=r"(r3) : "r"(addr))

#define MMA_BF16(d, a, b0, b1) \
    asm volatile("mma.sync.aligned.m16n8k16.row.col.f32.bf16.bf16.f32 " \
                 "{%0,%1,%2,%3}, {%4,%5,%6,%7}, {%8,%9}, {%0,%1,%2,%3};" \
                 : "+f"(d[0]), "+f"(d[1]), "+f"(d[2]), "+f"(d[3]) \
                 : "r"(a[0]), "r"(a[1]), "r"(a[2]), "r"(a[3]), "r"(b0), "r"(b1))

__device__ __forceinline__ uint32_t smem_u32(const void* p) {
    uint32_t a;
    asm("{ .reg .u64 t; cvta.to.shared.u64 t, %1; cvt.u32.u64 %0, t; }"
        : "=r"(a) : "l"(p));
    return a;
}
__device__ __forceinline__ float4 ld_cg_f4(const float* p) {
    float4 v;
    asm volatile("ld.global.cg.v4.f32 {%0,%1,%2,%3}, [%4];"
                 : "=f"(v.x), "=f"(v.y), "=f"(v.z), "=f"(v.w) : "l"(p));
    return v;
}
__device__ __forceinline__ void st_cg_f4(float* p, float4 v) {
    asm volatile("st.global.cg.v4.f32 [%0], {%1,%2,%3,%4};"
                 :: "l"(p), "f"(v.x), "f"(v.y), "f"(v.z), "f"(v.w) : "memory");
}

// Split one float4 (4 consecutive k) into bf16 hi/lo packed pairs.
__device__ __forceinline__ void cvt_hilo(float4 v, uint32_t& h0, uint32_t& h1,
                                         uint32_t& l0, uint32_t& l1) {
    __nv_bfloat162 a = __floats2bfloat162_rn(v.x, v.y);   // .x = v.x (low half = k)
    __nv_bfloat162 b = __floats2bfloat162_rn(v.z, v.w);
    __nv_bfloat162 al = __floats2bfloat162_rn(v.x - __bfloat162float(a.x),
                                              v.y - __bfloat162float(a.y));
    __nv_bfloat162 bl = __floats2bfloat162_rn(v.z - __bfloat162float(b.x),
                                              v.w - __bfloat162float(b.y));
    h0 = *(uint32_t*)&a;  h1 = *(uint32_t*)&b;
    l0 = *(uint32_t*)&al; l1 = *(uint32_t*)&bl;
}

// Persistent state: per-(layer,t) counters, zeroed each launch (graph-safe).
__device__ int g_cnt[Ln * SEQn];
__global__ void zero_cnt_kernel() { g_cnt[threadIdx.x] = 0; }

__global__ __launch_bounds__(NTHR, 1)
void rnn_kernel(const float* __restrict__ x,
                const float* __restrict__ w_ih,
                const float* __restrict__ b_ih,
                const float* __restrict__ w_hh,
                const float* __restrict__ b_hh,
                float* __restrict__ out)
{
    const int layer = blockIdx.x >> 5;
    const int cb    = blockIdx.x & (NBC - 1);
    const int j0    = cb * NJ;
    const int tid   = threadIdx.x;
    const int w     = tid >> 5;
    const int lane  = tid & 31;

    extern __shared__ __align__(16) char smem[];
    const uint32_t sb = smem_u32(smem);

    float* outputs = out;
    float* states  = out + SEQn * Bn * Hn;

    // ---- One-time: W = [Wih | Whh] (16 rows x 1024 k) -> bf16 hi/lo tiles ----
    for (int u = 0; u < 64; ++u) {
        int i = u * NTHR + tid;
        int j = i >> 10, k = i & 1023;
        float v = (k < 512)
            ? w_ih[(size_t)(layer * Hn + j0 + j) * Hn + k]
            : w_hh[(size_t)(layer * Hn + j0 + j) * Hn + (k - 512)];
        __nv_bfloat16 hi = __float2bfloat16(v);
        __nv_bfloat16 lo = __float2bfloat16(v - __bfloat162float(hi));
        *(__nv_bfloat16*)(smem + SM_WHI + j * WROWB + k * 2) = hi;
        *(__nv_bfloat16*)(smem + SM_WLO + j * WROWB + k * 2) = lo;
    }
    float4 bias4;
    {
        int jb = layer * Hn + j0 + (tid & 3) * 4;
        bias4.x = b_ih[jb + 0] + b_hh[jb + 0];
        bias4.y = b_ih[jb + 1] + b_hh[jb + 1];
        bias4.z = b_ih[jb + 2] + b_hh[jb + 2];
        bias4.w = b_ih[jb + 3] + b_hh[jb + 3];
    }
    __syncthreads();

    // ldmatrix lane-address components (standard m8n8.x4 tile order)
    const int tq = lane >> 3, rq = lane & 7;
    const int a_m_off = (tq & 1) * 8 + rq;        // + mt*16
    const int a_k_off = (tq >> 1) * 8;            // + w*16
    const int b_n     = (tq >> 1) * 8 + rq;
    const int b_k_off = (tq & 1) * 8;             // + c*128 + w*16

    for (int t = 0; t < SEQn; ++t) {
        // ---- Dependency wait (identical protocol to prior passing rounds) ----
        if (tid == 0) {
            volatile int* vc = g_cnt;
            if (t > 0) {
                int s = 0;
                while (vc[layer * SEQn + t - 1] < NBC) {
                    __nanosleep(40); if (++s > 1000000) break;
                }
            }
            if (layer > 0) {
                int s = 0;
                while (vc[(layer - 1) * SEQn + t] < NBC) {
                    __nanosleep(40); if (++s > 1000000) break;
                }
            }
            __threadfence();
        }
        __syncthreads();

        const float* inpA = (layer == 0)
            ? (x + (size_t)t * Bn * Hn)
            : (states + (size_t)(t * Ln + (layer - 1)) * Bn * Hn);
        const float* hA =
            states + (size_t)((t - 1) * Ln + layer) * Bn * Hn;  // unused at t==0
        const int ncc = (t == 0) ? 4 : NCHUNK;    // h(-1)=0: skip Whh chunks

        float D[4][2][4];
        #pragma unroll
        for (int mt = 0; mt < 4; ++mt)
            #pragma unroll
            for (int nt = 0; nt < 2; ++nt)
                #pragma unroll
                for (int q = 0; q < 4; ++q) D[mt][nt][q] = 0.f;

        // Stage chunk 0: LDG (.cg) -> bf16 hi/lo -> smem buf0
        float4 pf[8];
        #pragma unroll
        for (int u = 0; u < 8; ++u) {
            int f = u * NTHR + tid;                    // b = f>>5, k = (f&31)*4
            pf[u] = ld_cg_f4(inpA + (f >> 5) * Hn + (f & 31) * 4);
        }
        #pragma unroll
        for (int u = 0; u < 8; ++u) {
            int f = u * NTHR + tid;
            int b = f >> 5, k = (f & 31) * 4;
            uint32_t h0, h1, l0, l1;
            cvt_hilo(pf[u], h0, h1, l0, l1);
            char* base = smem + SM_A + b * AROWB + k * 2;
            *(uint2*)(base)              = make_uint2(h0, h1);   // hi tile (buf0)
            *(uint2*)(base + ATILEB)     = make_uint2(l0, l1);   // lo tile
        }
        __syncthreads();

        for (int c = 0; c < ncc; ++c) {
            const int buf = c & 1;

            if (c + 1 < ncc) {     // next-chunk LDGs issued before mma (hidden)
                const float* Asrc = ((c + 1) < 4) ? inpA : hA;
                int koff = ((c + 1) & 3) * KCH;
                #pragma unroll
                for (int u = 0; u < 8; ++u) {
                    int f = u * NTHR + tid;
                    pf[u] = ld_cg_f4(Asrc + (f >> 5) * Hn + koff + (f & 31) * 4);
                }
            }

            // ---- Tensor compute on chunk c (warp k-slice = w*16 .. +16) ----
            uint32_t bAddrH = sb + SM_WHI + b_n * WROWB
                              + (c * KCH + w * 16 + b_k_off) * 2;
            uint32_t bAddrL = bAddrH + (SM_WLO - SM_WHI);
            uint32_t bh[4], bl[4];
            LDSM4(bh[0], bh[1], bh[2], bh[3], bAddrH);
            LDSM4(bl[0], bl[1], bl[2], bl[3], bAddrL);

            uint32_t aBaseH = sb + SM_A + buf * 2 * ATILEB
                              + a_m_off * AROWB + (w * 16 + a_k_off) * 2;
            #pragma unroll
            for (int mt = 0; mt < 4; ++mt) {
                uint32_t ah[4];
                LDSM4(ah[0], ah[1], ah[2], ah[3], aBaseH + mt * 16 * AROWB);
                MMA_BF16(D[mt][0], ah, bh[0], bh[1]);
                MMA_BF16(D[mt][1], ah, bh[2], bh[3]);
                MMA_BF16(D[mt][0], ah, bl[0], bl[1]);
                MMA_BF16(D[mt][1], ah, bl[2], bl[3]);
            }
            #pragma unroll
            for (int mt = 0; mt < 4; ++mt) {
                uint32_t al[4];
                LDSM4(al[0], al[1], al[2], al[3],
                      aBaseH + ATILEB + mt * 16 * AROWB);
                MMA_BF16(D[mt][0], al, bh[0], bh[1]);
                MMA_BF16(D[mt][1], al, bh[2], bh[3]);
            }

            if (c + 1 < ncc) {     // convert + stage next chunk into other buffer
                char* abase = smem + SM_A + ((c + 1) & 1) * 2 * ATILEB;
                #pragma unroll
                for (int u = 0; u < 8; ++u) {
                    int f = u * NTHR + tid;
                    int b = f >> 5, k = (f & 31) * 4;
                    uint32_t h0, h1, l0, l1;
                    cvt_hilo(pf[u], h0, h1, l0, l1);
                    char* base = abase + b * AROWB + k * 2;
                    *(uint2*)(base)          = make_uint2(h0, h1);
                    *(uint2*)(base + ATILEB) = make_uint2(l0, l1);
                }
            }
            __syncthreads();
        }

        // ---- Split-K reduction across 8 warps via smem ----
        {
            float* red = (float*)(smem + SM_RED) + w * (64 * REDW);
            #pragma unroll
            for (int mt = 0; mt < 4; ++mt)
                #pragma unroll
                for (int nt = 0; nt < 2; ++nt) {
                    int m = mt * 16 + (lane >> 2);
                    int n = nt * 8 + 2 * (lane & 3);
                    *(float2*)(red + m * REDW + n) =
                        make_float2(D[mt][nt][0], D[mt][nt][1]);
                    *(float2*)(red + (m + 8) * REDW + n) =
                        make_float2(D[mt][nt][2], D[mt][nt][3]);
                }
        }
        __syncthreads();

        // Each thread finalizes 4 outputs: (b = tid>>2, j = j0 + (tid&3)*4 ..+3)
        {
            int b  = tid >> 2;
            int jq = (tid & 3) * 4;
            float4 acc = bias4;
            const float* redb = (const float*)(smem + SM_RED) + b * REDW + jq;
            #pragma unroll
            for (int w2 = 0; w2 < 8; ++w2) {
                float4 p = *(const float4*)(redb + w2 * (64 * REDW));
                acc.x += p.x; acc.y += p.y; acc.z += p.z; acc.w += p.w;
            }
            float4 v;
            v.x = tanhf(acc.x); v.y = tanhf(acc.y);
            v.z = tanhf(acc.z); v.w = tanhf(acc.w);
            float* sp = states + ((size_t)(t * Ln + layer) * Bn + b) * Hn + j0 + jq;
            st_cg_f4(sp, v);
            if (layer == Ln - 1) {
                float* op = outputs + ((size_t)t * Bn + b) * Hn + j0 + jq;
                st_cg_f4(op, v);
            }
        }

        // Publish step completion
        __threadfence();
        __syncthreads();
        if (tid == 0) atomicAdd(&g_cnt[layer * SEQn + t], 1);
    }
}

extern "C" void kernel_launch(void* const* d_in, const int* in_sizes, int n_in,
                              void* d_out, int out_size) {
    const float* x    = (const float*)d_in[0];   // [SEQ,B,H]
    const float* w_ih = (const float*)d_in[1];   // [L,H,H]
    const float* b_ih = (const float*)d_in[2];   // [L,H]
    const float* w_hh = (const float*)d_in[3];   // [L,H,H]
    const float* b_hh = (const float*)d_in[4];   // [L,H]
    float* out = (float*)d_out;                  // outputs ++ states

    cudaFuncSetAttribute(rnn_kernel,
                         cudaFuncAttributeMaxDynamicSharedMemorySize, SMEM_BYTES);

    zero_cnt_kernel<<<1, Ln * SEQn>>>();
    rnn_kernel<<<Ln * NBC, NTHR, SMEM_BYTES>>>(x, w_ih, b_ih, w_hh, b_hh, out);
}

// round 15
// speedup vs baseline: 2.5903x; 1.0897x over previous
#include <cuda_runtime.h>
#include <cuda_bf16.h>
#include <cstdint>

// Problem constants
#define SEQn 256
#define Bn   64
#define Hn   512
#define Ln   4
#define NJ   16       // output columns per block
#define NBC  32       // blocks per layer
#define NTHR 256      // 8 warps; warp w owns k-slice [w*32,w*32+32) of each 256-chunk
#define KCH  256      // k per staged chunk (2 inp + 2 h chunks)

// ---- SMEM byte map ----
// W tiles: [16 rows][1024 k] bf16, row stride 2064 B (516 words %32==4 -> CF).
// A tiles: [2 dbuf][hi|lo][64 rows][256 k] bf16, row stride 528 B (132 %32==4).
// RED (split-K partials) overlays the A region (A dead when RED is used).
#define WROWB  2064
#define SM_WHI 0
#define SM_WLO (16 * WROWB)              // 33,024
#define SM_A   (2 * 16 * WROWB)          // 66,048
#define AROWB  528
#define ATILEB (64 * AROWB)              // 33,792
#define ABUF   (2 * ATILEB)              // 67,584 (hi+lo)
#define SM_RED SM_A                      // overlay
#define REDW   20
#define SMEM_BYTES (SM_A + 2 * ABUF)     // 201,216 B

// ---- PTX helpers (baseline sm_80+) ----
#define LDSM4(r0, r1, r2, r3, addr) \
    asm volatile("ldmatrix.sync.aligned.m8n8.x4.shared.b16 {%0,%1,%2,%3}, [%4];" \
                 : "=r"(r0), "=r"(r1), "=r"(r2), "=r"(r3) : "r"(addr))

#define MMA_BF16(d, a, b0, b1) \
    asm volatile("mma.sync.aligned.m16n8k16.row.col.f32.bf16.bf16.f32 " \
                 "{%0,%1,%2,%3}, {%4,%5,%6,%7}, {%8,%9}, {%0,%1,%2,%3};" \
                 : "+f"(d[0]), "+f"(d[1]), "+f"(d[2]), "+f"(d[3]) \
                 : "r"(a[0]), "r"(a[1]), "r"(a[2]), "r"(a[3]), "r"(b0), "r"(b1))

__device__ __forceinline__ uint32_t smem_u32(const void* p) {
    uint32_t a;
    asm("{ .reg .u64 t; cvta.to.shared.u64 t, %1; cvt.u32.u64 %0, t; }"
        : "=r"(a) : "l"(p));
    return a;
}
__device__ __forceinline__ uint4 ld_cg_u4(const void* p) {
    uint4 v;
    asm volatile("ld.global.cg.v4.u32 {%0,%1,%2,%3}, [%4];"
                 : "=r"(v.x), "=r"(v.y), "=r"(v.z), "=r"(v.w) : "l"(p));
    return v;
}
__device__ __forceinline__ void st_cg_f4(float* p, float4 v) {
    asm volatile("st.global.cg.v4.f32 [%0], {%1,%2,%3,%4};"
                 :: "l"(p), "f"(v.x), "f"(v.y), "f"(v.z), "f"(v.w) : "memory");
}
__device__ __forceinline__ void st_cg_u2(void* p, uint32_t a, uint32_t b) {
    asm volatile("st.global.cg.v2.u32 [%0], {%1,%2};"
                 :: "l"(p), "r"(a), "r"(b) : "memory");
}

// Persistent scratch: bf16 hi/lo copies of states and x (write-once per cell).
// Static __device__ arrays (the sanctioned scratch mechanism; no allocs).
__device__ __nv_bfloat16 g_shi[(size_t)SEQn * Ln * Bn * Hn];
__device__ __nv_bfloat16 g_slo[(size_t)SEQn * Ln * Bn * Hn];
__device__ __nv_bfloat16 g_xhi[(size_t)SEQn * Bn * Hn];
__device__ __nv_bfloat16 g_xlo[(size_t)SEQn * Bn * Hn];

__device__ int g_cnt[Ln * SEQn];
__global__ void zero_cnt_kernel() { g_cnt[threadIdx.x] = 0; }

// Prologue: x -> bf16 hi/lo scratch (one-time, fully parallel).
__global__ void cvt_x_kernel(const float* __restrict__ x) {
    const int n4 = SEQn * Bn * Hn / 4;
    for (int i = blockIdx.x * blockDim.x + threadIdx.x; i < n4;
         i += gridDim.x * blockDim.x) {
        float4 v = ((const float4*)x)[i];
        __nv_bfloat162 h01 = __floats2bfloat162_rn(v.x, v.y);
        __nv_bfloat162 h23 = __floats2bfloat162_rn(v.z, v.w);
        __nv_bfloat162 l01 = __floats2bfloat162_rn(v.x - __bfloat162float(h01.x),
                                                   v.y - __bfloat162float(h01.y));
        __nv_bfloat162 l23 = __floats2bfloat162_rn(v.z - __bfloat162float(h23.x),
                                                   v.w - __bfloat162float(h23.y));
        ((uint2*)g_xhi)[i] = make_uint2(*(uint32_t*)&h01, *(uint32_t*)&h23);
        ((uint2*)g_xlo)[i] = make_uint2(*(uint32_t*)&l01, *(uint32_t*)&l23);
    }
}

__global__ __launch_bounds__(NTHR, 1)
void rnn_kernel(const float* __restrict__ x,
                const float* __restrict__ w_ih,
                const float* __restrict__ b_ih,
                const float* __restrict__ w_hh,
                const float* __restrict__ b_hh,
                float* __restrict__ out)
{
    const int layer = blockIdx.x >> 5;
    const int cb    = blockIdx.x & (NBC - 1);
    const int j0    = cb * NJ;
    const int tid   = threadIdx.x;
    const int w     = tid >> 5;
    const int lane  = tid & 31;

    extern __shared__ __align__(16) char smem[];
    const uint32_t sb = smem_u32(smem);

    float* outputs = out;
    float* states  = out + SEQn * Bn * Hn;

    // ---- One-time: W = [Wih | Whh] (16 rows x 1024 k) -> bf16 hi/lo tiles ----
    for (int u = 0; u < 64; ++u) {
        int i = u * NTHR + tid;
        int j = i >> 10, k = i & 1023;
        float v = (k < 512)
            ? w_ih[(size_t)(layer * Hn + j0 + j) * Hn + k]
            : w_hh[(size_t)(layer * Hn + j0 + j) * Hn + (k - 512)];
        __nv_bfloat16 hi = __float2bfloat16(v);
        __nv_bfloat16 lo = __float2bfloat16(v - __bfloat162float(hi));
        *(__nv_bfloat16*)(smem + SM_WHI + j * WROWB + k * 2) = hi;
        *(__nv_bfloat16*)(smem + SM_WLO + j * WROWB + k * 2) = lo;
    }
    float4 bias4;
    {
        int jb = layer * Hn + j0 + (tid & 3) * 4;
        bias4.x = b_ih[jb + 0] + b_hh[jb + 0];
        bias4.y = b_ih[jb + 1] + b_hh[jb + 1];
        bias4.z = b_ih[jb + 2] + b_hh[jb + 2];
        bias4.w = b_ih[jb + 3] + b_hh[jb + 3];
    }
    __syncthreads();

    // ldmatrix lane-address components (validated in R14)
    const int tq = lane >> 3, rq = lane & 7;
    const int a_m_off = (tq & 1) * 8 + rq;
    const int a_k_off = (tq >> 1) * 8;
    const int b_n     = (tq >> 1) * 8 + rq;
    const int b_k_off = (tq & 1) * 8;

    for (int t = 0; t < SEQn; ++t) {
        // ---- Dependency wait (identical protocol to prior passing rounds) ----
        if (tid == 0) {
            volatile int* vc = g_cnt;
            if (t > 0) {
                int s = 0;
                while (vc[layer * SEQn + t - 1] < NBC) {
                    __nanosleep(20); if (++s > 2000000) break;
                }
            }
            if (layer > 0) {
                int s = 0;
                while (vc[(layer - 1) * SEQn + t] < NBC) {
                    __nanosleep(20); if (++s > 2000000) break;
                }
            }
            __threadfence();
        }
        __syncthreads();

        // bf16 hi/lo activation sources (scratch; always .cg)
        const __nv_bfloat16* inpHi = (layer == 0)
            ? (g_xhi + (size_t)t * Bn * Hn)
            : (g_shi + (size_t)(t * Ln + (layer - 1)) * Bn * Hn);
        const __nv_bfloat16* inpLo = (layer == 0)
            ? (g_xlo + (size_t)t * Bn * Hn)
            : (g_slo + (size_t)(t * Ln + (layer - 1)) * Bn * Hn);
        const __nv_bfloat16* hHi = g_shi + (size_t)((t - 1) * Ln + layer) * Bn * Hn;
        const __nv_bfloat16* hLo = g_slo + (size_t)((t - 1) * Ln + layer) * Bn * Hn;
        const int ncc = (t == 0) ? 2 : 4;   // chunks 0,1 = inp; 2,3 = h

        float D[4][2][4];
        #pragma unroll
        for (int mt = 0; mt < 4; ++mt)
            #pragma unroll
            for (int nt = 0; nt < 2; ++nt)
                #pragma unroll
                for (int q = 0; q < 4; ++q) D[mt][nt][q] = 0.f;

        // Stage chunk 0 (pure copy: LDG.cg bf16 -> STS)
        uint4 pf[16];
        #pragma unroll
        for (int u = 0; u < 16; ++u) {
            int f = (u & 7) * NTHR + tid;      // row = f>>5, c4 = f&31 (16B units)
            const __nv_bfloat16* src = (u < 8) ? inpHi : inpLo;
            pf[u] = ld_cg_u4(src + (f >> 5) * Hn + (f & 31) * 8);
        }
        #pragma unroll
        for (int u = 0; u < 16; ++u) {
            int f = (u & 7) * NTHR + tid;
            char* dst = smem + SM_A + ((u < 8) ? 0 : ATILEB)
                        + (f >> 5) * AROWB + (f & 31) * 16;
            *(uint4*)dst = pf[u];
        }
        __syncthreads();

        for (int c = 0; c < ncc; ++c) {
            const int buf = c & 1;

            if (c + 1 < ncc) {     // next-chunk LDGs first (hidden under mma)
                const __nv_bfloat16* sH = ((c + 1) < 2) ? inpHi : hHi;
                const __nv_bfloat16* sL = ((c + 1) < 2) ? inpLo : hLo;
                int koff = ((c + 1) & 1) * KCH;
                #pragma unroll
                for (int u = 0; u < 16; ++u) {
                    int f = (u & 7) * NTHR + tid;
                    const __nv_bfloat16* src = (u < 8) ? sH : sL;
                    pf[u] = ld_cg_u4(src + (f >> 5) * Hn + koff + (f & 31) * 8);
                }
            }

            // ---- Tensor compute: warp k-slice = c*256 + w*32 .. +32 ----
            #pragma unroll
            for (int ks = 0; ks < 2; ++ks) {
                int kg = c * KCH + w * 32 + ks * 16;
                uint32_t bAddrH = sb + SM_WHI + b_n * WROWB + (kg + b_k_off) * 2;
                uint32_t bAddrL = bAddrH + (SM_WLO - SM_WHI);
                uint32_t bh[4], bl[4];
                LDSM4(bh[0], bh[1], bh[2], bh[3], bAddrH);
                LDSM4(bl[0], bl[1], bl[2], bl[3], bAddrL);

                uint32_t aBase = sb + SM_A + buf * ABUF + a_m_off * AROWB
                                 + (w * 32 + ks * 16 + a_k_off) * 2;
                #pragma unroll
                for (int mt = 0; mt < 4; ++mt) {
                    uint32_t ah[4];
                    LDSM4(ah[0], ah[1], ah[2], ah[3], aBase + mt * 16 * AROWB);
                    MMA_BF16(D[mt][0], ah, bh[0], bh[1]);
                    MMA_BF16(D[mt][1], ah, bh[2], bh[3]);
                    MMA_BF16(D[mt][0], ah, bl[0], bl[1]);
                    MMA_BF16(D[mt][1], ah, bl[2], bl[3]);
                }
                #pragma unroll
                for (int mt = 0; mt < 4; ++mt) {
                    uint32_t al[4];
                    LDSM4(al[0], al[1], al[2], al[3],
                          aBase + ATILEB + mt * 16 * AROWB);
                    MMA_BF16(D[mt][0], al, bh[0], bh[1]);
                    MMA_BF16(D[mt][1], al, bh[2], bh[3]);
                }
            }

            if (c + 1 < ncc) {     // stage next chunk into other buffer
                char* abase = smem + SM_A + ((c + 1) & 1) * ABUF;
                #pragma unroll
                for (int u = 0; u < 16; ++u) {
                    int f = (u & 7) * NTHR + tid;
                    char* dst = abase + ((u < 8) ? 0 : ATILEB)
                                + (f >> 5) * AROWB + (f & 31) * 16;
                    *(uint4*)dst = pf[u];
                }
            }
            __syncthreads();
        }

        // ---- Split-K reduction across 8 warps (RED overlays dead A region) ----
        {
            float* red = (float*)(smem + SM_RED) + w * (64 * REDW);
            #pragma unroll
            for (int mt = 0; mt < 4; ++mt)
                #pragma unroll
                for (int nt = 0; nt < 2; ++nt) {
                    int m = mt * 16 + (lane >> 2);
                    int n = nt * 8 + 2 * (lane & 3);
                    *(float2*)(red + m * REDW + n) =
                        make_float2(D[mt][nt][0], D[mt][nt][1]);
                    *(float2*)(red + (m + 8) * REDW + n) =
                        make_float2(D[mt][nt][2], D[mt][nt][3]);
                }
        }
        __syncthreads();

        // Finalize 4 outputs/thread: b = tid>>2, j = j0 + (tid&3)*4 .. +3
        {
            int b  = tid >> 2;
            int jq = (tid & 3) * 4;
            float4 acc = bias4;
            const float* redb = (const float*)(smem + SM_RED) + b * REDW + jq;
            #pragma unroll
            for (int w2 = 0; w2 < 8; ++w2) {
                float4 p = *(const float4*)(redb + w2 * (64 * REDW));
                acc.x += p.x; acc.y += p.y; acc.z += p.z; acc.w += p.w;
            }
            float4 v;
            v.x = tanhf(acc.x); v.y = tanhf(acc.y);
            v.z = tanhf(acc.z); v.w = tanhf(acc.w);

            size_t sidx = ((size_t)(t * Ln + layer) * Bn + b) * Hn + j0 + jq;
            st_cg_f4(states + sidx, v);
            if (layer == Ln - 1) {
                float* op = outputs + ((size_t)t * Bn + b) * Hn + j0 + jq;
                st_cg_f4(op, v);
            }
            // Publish bf16 hi/lo for downstream consumers (only our 4 values)
            __nv_bfloat162 h01 = __floats2bfloat162_rn(v.x, v.y);
            __nv_bfloat162 h23 = __floats2bfloat162_rn(v.z, v.w);
            __nv_bfloat162 l01 = __floats2bfloat162_rn(
                v.x - __bfloat162float(h01.x), v.y - __bfloat162float(h01.y));
            __nv_bfloat162 l23 = __floats2bfloat162_rn(
                v.z - __bfloat162float(h23.x), v.w - __bfloat162float(h23.y));
            st_cg_u2(g_shi + sidx, *(uint32_t*)&h01, *(uint32_t*)&h23);
            st_cg_u2(g_slo + sidx, *(uint32_t*)&l01, *(uint32_t*)&l23);
        }

        // Publish step completion (release)
        __threadfence();
        __syncthreads();
        if (tid == 0) atomicAdd(&g_cnt[layer * SEQn + t], 1);
    }
}

extern "C" void kernel_launch(void* const* d_in, const int* in_sizes, int n_in,
                              void* d_out, int out_size) {
    const float* x    = (const float*)d_in[0];   // [SEQ,B,H]
    const float* w_ih = (const float*)d_in[1];   // [L,H,H]
    const float* b_ih = (const float*)d_in[2];   // [L,H]
    const float* w_hh = (const float*)d_in[3];   // [L,H,H]
    const float* b_hh = (const float*)d_in[4];   // [L,H]
    float* out = (float*)d_out;                  // outputs ++ states

    cudaFuncSetAttribute(rnn_kernel,
                         cudaFuncAttributeMaxDynamicSharedMemorySize, SMEM_BYTES);

    zero_cnt_kernel<<<1, Ln * SEQn>>>();
    cvt_x_kernel<<<1024, 256>>>(x);
    rnn_kernel<<<Ln * NBC, NTHR, SMEM_BYTES>>>(x, w_ih, b_ih, w_hh, b_hh, out);
}